// round 1
// baseline (speedup 1.0000x reference)
#include <cuda_runtime.h>

// Problem constants
#define BD    8
#define TD    4096
#define DD    512
#define DIE   1024          // DI
#define NROWS (BD*TD)       // 32768
#define LN_EPS 1e-5f

// ---------------- scratch (no cudaMalloc allowed) ----------------
__device__ float g_xz[(size_t)NROWS * 2 * DIE];   // 256 MB  [m][0..1023]=x_proj, [1024..2047]=z
__device__ float g_cf[(size_t)NROWS * DIE];       // 128 MB  causal conv fwd
__device__ float g_cb[(size_t)NROWS * DIE];       // 128 MB  anti-causal conv bwd (pre-shift form)
__device__ float g_pf[(size_t)NROWS * DIE];       // 128 MB  silu(proj_fwd)
__device__ float g_pb[(size_t)NROWS * DIE];       // 128 MB  silu(proj_bwd)
__device__ float g_y [(size_t)NROWS * DIE];       // 128 MB  gated mix
__device__ float g_o [(size_t)NROWS * DD];        //  64 MB  out_proj result

__device__ __forceinline__ float silu_f(float v) {
    return v / (1.f + __expf(-v));
}

// ---------------- SGEMM: C[M,N] = A[M,K] * B[N,K]^T  (both row-major, NT) --------
// 128x128x16 tiles, 256 threads, 8x8 per-thread, double-buffered smem.
// EPI==0: C = acc            EPI==1: C = silu(acc + bias[n])
template<int EPI>
__global__ void __launch_bounds__(256, 2)
sgemm_nt(const float* __restrict__ A, const float* __restrict__ B,
         const float* __restrict__ bias, float* __restrict__ C,
         int M, int N, int K)
{
    __shared__ float As[2][16][128 + 4];
    __shared__ float Bs[2][16][128 + 4];

    const int tid  = threadIdx.x;
    const int lrow = tid >> 2;          // 0..63
    const int lcol = (tid & 3) << 2;    // 0,4,8,12
    const int ty   = tid >> 4;          // 0..15
    const int tx   = tid & 15;          // 0..15

    const size_t row0 = (size_t)blockIdx.y * 128;
    const size_t col0 = (size_t)blockIdx.x * 128;

    const float* Ap = A + (row0 + lrow) * (size_t)K + lcol;
    const float* Bp = B + (col0 + lrow) * (size_t)K + lcol;
    const size_t strideR64 = (size_t)64 * K;

    float acc[8][8];
#pragma unroll
    for (int i = 0; i < 8; i++)
#pragma unroll
        for (int j = 0; j < 8; j++) acc[i][j] = 0.f;

    const int KT = K >> 4;

    float4 ra0, ra1, rb0, rb1;

    // preload tile 0
    ra0 = *(const float4*)(Ap);
    ra1 = *(const float4*)(Ap + strideR64);
    rb0 = *(const float4*)(Bp);
    rb1 = *(const float4*)(Bp + strideR64);
    As[0][lcol + 0][lrow]      = ra0.x; As[0][lcol + 1][lrow]      = ra0.y;
    As[0][lcol + 2][lrow]      = ra0.z; As[0][lcol + 3][lrow]      = ra0.w;
    As[0][lcol + 0][lrow + 64] = ra1.x; As[0][lcol + 1][lrow + 64] = ra1.y;
    As[0][lcol + 2][lrow + 64] = ra1.z; As[0][lcol + 3][lrow + 64] = ra1.w;
    Bs[0][lcol + 0][lrow]      = rb0.x; Bs[0][lcol + 1][lrow]      = rb0.y;
    Bs[0][lcol + 2][lrow]      = rb0.z; Bs[0][lcol + 3][lrow]      = rb0.w;
    Bs[0][lcol + 0][lrow + 64] = rb1.x; Bs[0][lcol + 1][lrow + 64] = rb1.y;
    Bs[0][lcol + 2][lrow + 64] = rb1.z; Bs[0][lcol + 3][lrow + 64] = rb1.w;
    __syncthreads();

    for (int kt = 0; kt < KT; ++kt) {
        const int cur = kt & 1;
        if (kt + 1 < KT) {
            const float* Ap2 = Ap + (size_t)(kt + 1) * 16;
            const float* Bp2 = Bp + (size_t)(kt + 1) * 16;
            ra0 = *(const float4*)(Ap2);
            ra1 = *(const float4*)(Ap2 + strideR64);
            rb0 = *(const float4*)(Bp2);
            rb1 = *(const float4*)(Bp2 + strideR64);
        }
#pragma unroll
        for (int k = 0; k < 16; k++) {
            float4 a0 = *(const float4*)&As[cur][k][ty * 8];
            float4 a1 = *(const float4*)&As[cur][k][ty * 8 + 4];
            float4 b0 = *(const float4*)&Bs[cur][k][tx * 8];
            float4 b1 = *(const float4*)&Bs[cur][k][tx * 8 + 4];
            float av[8] = {a0.x, a0.y, a0.z, a0.w, a1.x, a1.y, a1.z, a1.w};
            float bv[8] = {b0.x, b0.y, b0.z, b0.w, b1.x, b1.y, b1.z, b1.w};
#pragma unroll
            for (int i = 0; i < 8; i++)
#pragma unroll
                for (int j = 0; j < 8; j++)
                    acc[i][j] = fmaf(av[i], bv[j], acc[i][j]);
        }
        if (kt + 1 < KT) {
            const int nxt = cur ^ 1;
            As[nxt][lcol + 0][lrow]      = ra0.x; As[nxt][lcol + 1][lrow]      = ra0.y;
            As[nxt][lcol + 2][lrow]      = ra0.z; As[nxt][lcol + 3][lrow]      = ra0.w;
            As[nxt][lcol + 0][lrow + 64] = ra1.x; As[nxt][lcol + 1][lrow + 64] = ra1.y;
            As[nxt][lcol + 2][lrow + 64] = ra1.z; As[nxt][lcol + 3][lrow + 64] = ra1.w;
            Bs[nxt][lcol + 0][lrow]      = rb0.x; Bs[nxt][lcol + 1][lrow]      = rb0.y;
            Bs[nxt][lcol + 2][lrow]      = rb0.z; Bs[nxt][lcol + 3][lrow]      = rb0.w;
            Bs[nxt][lcol + 0][lrow + 64] = rb1.x; Bs[nxt][lcol + 1][lrow + 64] = rb1.y;
            Bs[nxt][lcol + 2][lrow + 64] = rb1.z; Bs[nxt][lcol + 3][lrow + 64] = rb1.w;
        }
        __syncthreads();
    }

    // epilogue
    float bvals[8];
    if (EPI == 1) {
        *(float4*)&bvals[0] = *(const float4*)(bias + col0 + tx * 8);
        *(float4*)&bvals[4] = *(const float4*)(bias + col0 + tx * 8 + 4);
    }
#pragma unroll
    for (int i = 0; i < 8; i++) {
        float* Crow = C + (row0 + ty * 8 + i) * (size_t)N + col0 + tx * 8;
        float v[8];
#pragma unroll
        for (int j = 0; j < 8; j++) {
            float t = acc[i][j];
            if (EPI == 1) { t += bvals[j]; t = silu_f(t); }
            v[j] = t;
        }
        *(float4*)(Crow)     = make_float4(v[0], v[1], v[2], v[3]);
        *(float4*)(Crow + 4) = make_float4(v[4], v[5], v[6], v[7]);
    }
}

// ---------------- fused depthwise causal (fwd) + anti-causal (bwd) conv ----------
// cf[m,c] = bf[c] + sum_k  x_proj[m-6+k, c] * wf[c,k]          (t-6+k >= 0)
// cb[m,c] = bb[c] + sum_j  x_proj[m+1+j, c] * wb[c,6-j]        (t+1+j <  T)
// (the bwd form already folds in flip + shift_right + flip; y_bwd[t]=pb[t] for t<T-1)
__global__ void conv_dw(const float* __restrict__ xz,
                        const float* __restrict__ wf, const float* __restrict__ bf,
                        const float* __restrict__ wb, const float* __restrict__ bb,
                        float* __restrict__ cf, float* __restrict__ cb)
{
    long long id = (long long)blockIdx.x * blockDim.x + threadIdx.x;
    int c = (int)(id & (DIE - 1));
    long long m = id >> 10;
    int t = (int)(m & (TD - 1));
    long long base = m * (2 * DIE) + c;

    float accf = bf[c];
    float accb = bb[c];
#pragma unroll
    for (int k = 0; k < 7; k++) {
        float w = wf[c * 7 + k];
        float v = (t - 6 + k >= 0) ? xz[base + (long long)(k - 6) * (2 * DIE)] : 0.f;
        accf = fmaf(v, w, accf);
    }
#pragma unroll
    for (int j = 0; j < 7; j++) {
        float w = wb[c * 7 + (6 - j)];
        float v = (t + 1 + j < TD) ? xz[base + (long long)(j + 1) * (2 * DIE)] : 0.f;
        accb = fmaf(v, w, accb);
    }
    cf[id] = accf;
    cb[id] = accb;
}

// ---------------- combine: shifts + diag + gate -------------------------------
// y[m,e] = (pf[m-1,e]{t>0} + pb[m,e]{t<T-1} + x_proj[m,e]*diag[e]) * silu(z[m,e]) * gate
__global__ void combine_k(const float* __restrict__ xz,
                          const float* __restrict__ pf, const float* __restrict__ pb,
                          const float* __restrict__ diag, const float* __restrict__ gate,
                          float* __restrict__ y)
{
    long long id = (long long)blockIdx.x * blockDim.x + threadIdx.x;
    int e = (int)(id & (DIE - 1));
    long long m = id >> 10;
    int t = (int)(m & (TD - 1));

    float yf = (t > 0)      ? pf[id - DIE] : 0.f;
    float yb = (t < TD - 1) ? pb[id]       : 0.f;
    float xp = xz[m * (2 * DIE) + e];
    float z  = xz[m * (2 * DIE) + DIE + e];
    y[id] = (yf + yb + xp * diag[e]) * silu_f(z) * gate[0];
}

// ---------------- residual + LayerNorm(512) -----------------------------------
__device__ __forceinline__ float warp_sum(float v) {
#pragma unroll
    for (int o = 16; o > 0; o >>= 1) v += __shfl_down_sync(0xffffffffu, v, o);
    return v;
}

__global__ void ln_kernel(const float* __restrict__ x, const float* __restrict__ o,
                          const float* __restrict__ g, const float* __restrict__ b,
                          float* __restrict__ out)
{
    const int m = blockIdx.x;
    const int tid = threadIdx.x;   // 128 threads, float4 each = 512
    const size_t base = (size_t)m * DD;

    float4 xv = ((const float4*)(x + base))[tid];
    float4 ov = ((const float4*)(o + base))[tid];
    float4 h = make_float4(xv.x + ov.x, xv.y + ov.y, xv.z + ov.z, xv.w + ov.w);

    float s  = h.x + h.y + h.z + h.w;
    float ss = h.x * h.x + h.y * h.y + h.z * h.z + h.w * h.w;

    __shared__ float sh[4], sh2[4];
    float ws  = warp_sum(s);
    float wss = warp_sum(ss);
    if ((tid & 31) == 0) { sh[tid >> 5] = ws; sh2[tid >> 5] = wss; }
    __syncthreads();
    if (tid < 32) {
        float a  = (tid < 4) ? sh[tid]  : 0.f;
        float a2 = (tid < 4) ? sh2[tid] : 0.f;
        a  = warp_sum(a);
        a2 = warp_sum(a2);
        if (tid == 0) { sh[0] = a; sh2[0] = a2; }
    }
    __syncthreads();

    float mu  = sh[0] * (1.f / DD);
    float var = sh2[0] * (1.f / DD) - mu * mu;
    float inv = rsqrtf(var + LN_EPS);

    float4 gv = ((const float4*)g)[tid];
    float4 bv = ((const float4*)b)[tid];
    float4 r;
    r.x = (h.x - mu) * inv * gv.x + bv.x;
    r.y = (h.y - mu) * inv * gv.y + bv.y;
    r.z = (h.z - mu) * inv * gv.z + bv.z;
    r.w = (h.w - mu) * inv * gv.w + bv.w;
    ((float4*)(out + base))[tid] = r;
}

// ---------------- launch ------------------------------------------------------
extern "C" void kernel_launch(void* const* d_in, const int* in_sizes, int n_in,
                              void* d_out, int out_size)
{
    const float* x          = (const float*)d_in[0];
    const float* in_proj_w  = (const float*)d_in[1];
    const float* conv_fwd_w = (const float*)d_in[2];
    const float* conv_fwd_b = (const float*)d_in[3];
    const float* proj_fwd_w = (const float*)d_in[4];
    const float* proj_fwd_b = (const float*)d_in[5];
    const float* conv_bwd_w = (const float*)d_in[6];
    const float* conv_bwd_b = (const float*)d_in[7];
    const float* proj_bwd_w = (const float*)d_in[8];
    const float* proj_bwd_b = (const float*)d_in[9];
    const float* diag       = (const float*)d_in[10];
    const float* gate       = (const float*)d_in[11];
    const float* out_proj_w = (const float*)d_in[12];
    const float* ln_g       = (const float*)d_in[13];
    const float* ln_b       = (const float*)d_in[14];

    float *xz, *cf, *cb, *pf, *pb, *y, *o;
    cudaGetSymbolAddress((void**)&xz, g_xz);
    cudaGetSymbolAddress((void**)&cf, g_cf);
    cudaGetSymbolAddress((void**)&cb, g_cb);
    cudaGetSymbolAddress((void**)&pf, g_pf);
    cudaGetSymbolAddress((void**)&pb, g_pb);
    cudaGetSymbolAddress((void**)&y,  g_y);
    cudaGetSymbolAddress((void**)&o,  g_o);

    const dim3 thr(256);

    // 1) xz = x @ in_proj_w^T          (32768 x 2048, K=512)
    sgemm_nt<0><<<dim3(2048 / 128, NROWS / 128), thr>>>(x, in_proj_w, nullptr, xz,
                                                        NROWS, 2048, DD);
    // 2) both depthwise convs
    conv_dw<<<(NROWS * DIE) / 256, 256>>>(xz, conv_fwd_w, conv_fwd_b,
                                          conv_bwd_w, conv_bwd_b, cf, cb);
    // 3) pf = silu(cf @ proj_fwd_w^T + b)   (32768 x 1024, K=1024)
    sgemm_nt<1><<<dim3(DIE / 128, NROWS / 128), thr>>>(cf, proj_fwd_w, proj_fwd_b, pf,
                                                       NROWS, DIE, DIE);
    // 4) pb = silu(cb @ proj_bwd_w^T + b)
    sgemm_nt<1><<<dim3(DIE / 128, NROWS / 128), thr>>>(cb, proj_bwd_w, proj_bwd_b, pb,
                                                       NROWS, DIE, DIE);
    // 5) y = (shift(pf) + mask(pb) + x_proj*diag) * silu(z) * gate
    combine_k<<<(NROWS * DIE) / 256, 256>>>(xz, pf, pb, diag, gate, y);
    // 6) o = y @ out_proj_w^T          (32768 x 512, K=1024)
    sgemm_nt<0><<<dim3(DD / 128, NROWS / 128), thr>>>(y, out_proj_w, nullptr, o,
                                                      NROWS, DD, DIE);
    // 7) out = LayerNorm(x + o)
    ln_kernel<<<NROWS, 128>>>(x, o, ln_g, ln_b, (float*)d_out);
}

// round 3
// speedup vs baseline: 3.8606x; 3.8606x over previous
#include <cuda_runtime.h>
#include <cstdint>

// Problem constants
#define BD    8
#define TD    4096
#define DD    512
#define DIE   1024          // DI
#define NROWS (BD*TD)       // 32768
#define LN_EPS 1e-5f

// ---------------- scratch (no cudaMalloc allowed) ----------------
__device__ float g_xz[(size_t)NROWS * 2 * DIE];
__device__ float g_cf[(size_t)NROWS * DIE];
__device__ float g_cb[(size_t)NROWS * DIE];
__device__ float g_pf[(size_t)NROWS * DIE];
__device__ float g_pb[(size_t)NROWS * DIE];
__device__ float g_y [(size_t)NROWS * DIE];
__device__ float g_o [(size_t)NROWS * DD];

__device__ __forceinline__ float silu_f(float v) {
    return v / (1.f + __expf(-v));
}

__device__ __forceinline__ uint32_t f2tf32(float f) {
    uint32_t u;
    asm("cvt.rna.tf32.f32 %0, %1;" : "=r"(u) : "f"(f));
    return u;
}

__device__ __forceinline__ void mma_tf32(float* c, const uint4& a,
                                         uint32_t b0, uint32_t b1) {
    asm volatile(
        "mma.sync.aligned.m16n8k8.row.col.f32.tf32.tf32.f32 "
        "{%0,%1,%2,%3}, {%4,%5,%6,%7}, {%8,%9}, {%0,%1,%2,%3};"
        : "+f"(c[0]), "+f"(c[1]), "+f"(c[2]), "+f"(c[3])
        : "r"(a.x), "r"(a.y), "r"(a.z), "r"(a.w), "r"(b0), "r"(b1));
}

// =============== tf32 mma.sync GEMM: C[M,N] = A[M,K] * B[N,K]^T ===============
// 128x128x32 block, 256 threads, 8 warps (4M x 2N), warp tile 32x64.
// Smem stores operands in mma-fragment-major layout:
//   A word  = ((mt*4 + s)*32 + (lane_raw ^ s))*4 + reg    (16KB / buffer)
//   B word  = 16384/4 offset later; ((pj*4 + s)*32 + (lane_raw ^ s))*4 + reg4
// where for element (r, k): s=k>>3, kk=k&7, mt=r>>4, rr=r&15,
//   lane_raw = ((rr&7)<<2)|(kk&3), reg = (rr>>3) | ((kk>>2)<<1)
// and for B (n, k): nt=n>>3, nn=n&7, lane_raw=(nn<<2)|(kk&3),
//   pj=nt>>1, reg4=((nt&1)<<1)|(kk>>2)
// Compute side: LDS.128 at ((blk)*32 + (l^s))*4 -> conflict-free.
template<int EPI>
__global__ void __launch_bounds__(256, 1)
gemm_mma(const float* __restrict__ A, const float* __restrict__ B,
         const float* __restrict__ bias, float* __restrict__ C,
         int M, int N, int K)
{
    extern __shared__ uint32_t sm[];
    // words: A0[0..4095] B0[4096..8191] A1[8192..] B1[12288..]
    const int tid = threadIdx.x;
    const int wid = tid >> 5, l = tid & 31;
    const int wm = wid >> 1, wn = wid & 1;
    const int g = l >> 2, q = l & 3;

    const size_t row0 = (size_t)blockIdx.y * 128;
    const size_t col0 = (size_t)blockIdx.x * 128;

    const float* Ag = A + row0 * (size_t)K;
    const float* Bg = B + col0 * (size_t)K;

    // per-thread load coords: idx = tid + i*256 -> r=idx>>3, kg=idx&7
    int rr_[4], kg_[4];
#pragma unroll
    for (int i = 0; i < 4; i++) {
        int idx = tid + i * 256;
        rr_[i] = idx >> 3;
        kg_[i] = idx & 7;
    }

    float4 stgA[4], stgB[4];
    float acc[2][8][4];
#pragma unroll
    for (int mi = 0; mi < 2; mi++)
#pragma unroll
        for (int j = 0; j < 8; j++)
#pragma unroll
            for (int t = 0; t < 4; t++) acc[mi][j][t] = 0.f;

    const int NC = K >> 5;

    // ---- load chunk 0
#pragma unroll
    for (int i = 0; i < 4; i++) {
        stgA[i] = *(const float4*)(Ag + (size_t)rr_[i] * K + kg_[i] * 4);
        stgB[i] = *(const float4*)(Bg + (size_t)rr_[i] * K + kg_[i] * 4);
    }
    // ---- store chunk 0 to buffer 0
#pragma unroll
    for (int i = 0; i < 4; i++) {
        int r = rr_[i], kg = kg_[i], s = kg >> 1;
        int mt = r >> 4, rr = r & 15;
        int regA = (rr >> 3) | ((kg & 1) << 1);
        int nt = r >> 3, nn = r & 7;
        int regB = ((nt & 1) << 1) | (kg & 1);
        const float* va = (const float*)&stgA[i];
        const float* vb = (const float*)&stgB[i];
#pragma unroll
        for (int d = 0; d < 4; d++) {
            int laneA = (((rr & 7) << 2) | d) ^ s;
            sm[((mt * 4 + s) * 32 + laneA) * 4 + regA] = f2tf32(va[d]);
            int laneB = ((nn << 2) | d) ^ s;
            sm[4096 + (((nt >> 1) * 4 + s) * 32 + laneB) * 4 + regB] = f2tf32(vb[d]);
        }
    }
    __syncthreads();

    for (int c = 0; c < NC; ++c) {
        // prefetch next chunk from gmem
        if (c + 1 < NC) {
            const float* Ag2 = Ag + (size_t)(c + 1) * 32;
            const float* Bg2 = Bg + (size_t)(c + 1) * 32;
#pragma unroll
            for (int i = 0; i < 4; i++) {
                stgA[i] = *(const float4*)(Ag2 + (size_t)rr_[i] * K + kg_[i] * 4);
                stgB[i] = *(const float4*)(Bg2 + (size_t)rr_[i] * K + kg_[i] * 4);
            }
        }
        // compute on buffer c&1
        const uint32_t* As = sm + (c & 1) * 8192;
        const uint32_t* Bs = As + 4096;
#pragma unroll
        for (int s = 0; s < 4; s++) {
            const int ls = l ^ s;
            uint4 af[2], bf[4];
#pragma unroll
            for (int mi = 0; mi < 2; mi++) {
                int mt = wm * 2 + mi;
                af[mi] = *(const uint4*)&As[((mt * 4 + s) * 32 + ls) * 4];
            }
#pragma unroll
            for (int jj = 0; jj < 4; jj++) {
                int pj = wn * 4 + jj;
                bf[jj] = *(const uint4*)&Bs[((pj * 4 + s) * 32 + ls) * 4];
            }
#pragma unroll
            for (int mi = 0; mi < 2; mi++)
#pragma unroll
                for (int jj = 0; jj < 4; jj++) {
                    mma_tf32(acc[mi][jj * 2],     af[mi], bf[jj].x, bf[jj].y);
                    mma_tf32(acc[mi][jj * 2 + 1], af[mi], bf[jj].z, bf[jj].w);
                }
        }
        // store next chunk to other buffer
        if (c + 1 < NC) {
            uint32_t* Ad = sm + ((c + 1) & 1) * 8192;
            uint32_t* Bd = Ad + 4096;
#pragma unroll
            for (int i = 0; i < 4; i++) {
                int r = rr_[i], kg = kg_[i], s = kg >> 1;
                int mt = r >> 4, rr = r & 15;
                int regA = (rr >> 3) | ((kg & 1) << 1);
                int nt = r >> 3, nn = r & 7;
                int regB = ((nt & 1) << 1) | (kg & 1);
                const float* va = (const float*)&stgA[i];
                const float* vb = (const float*)&stgB[i];
#pragma unroll
                for (int d = 0; d < 4; d++) {
                    int laneA = (((rr & 7) << 2) | d) ^ s;
                    Ad[((mt * 4 + s) * 32 + laneA) * 4 + regA] = f2tf32(va[d]);
                    int laneB = ((nn << 2) | d) ^ s;
                    Bd[(((nt >> 1) * 4 + s) * 32 + laneB) * 4 + regB] = f2tf32(vb[d]);
                }
            }
        }
        __syncthreads();
    }

    // ---- epilogue: acc[mi][j] covers rows row0+wm*32+mi*16+{g,g+8},
    //      cols col0+wn*64+j*8+{q*2, q*2+1}
#pragma unroll
    for (int mi = 0; mi < 2; mi++) {
        size_t r1 = row0 + wm * 32 + mi * 16 + g;
#pragma unroll
        for (int j = 0; j < 8; j++) {
            size_t col = col0 + wn * 64 + j * 8 + q * 2;
            float v00 = acc[mi][j][0], v01 = acc[mi][j][1];
            float v10 = acc[mi][j][2], v11 = acc[mi][j][3];
            if (EPI == 1) {
                float2 bb = *(const float2*)(bias + col);
                v00 = silu_f(v00 + bb.x); v01 = silu_f(v01 + bb.y);
                v10 = silu_f(v10 + bb.x); v11 = silu_f(v11 + bb.y);
            }
            *(float2*)(C + r1 * N + col)       = make_float2(v00, v01);
            *(float2*)(C + (r1 + 8) * N + col) = make_float2(v10, v11);
        }
    }
}

// ---------------- fused depthwise causal (fwd) + anti-causal (bwd) conv ----------
__global__ void conv_dw(const float* __restrict__ xz,
                        const float* __restrict__ wf, const float* __restrict__ bf,
                        const float* __restrict__ wb, const float* __restrict__ bb,
                        float* __restrict__ cf, float* __restrict__ cb)
{
    long long id = (long long)blockIdx.x * blockDim.x + threadIdx.x;
    int c = (int)(id & (DIE - 1));
    long long m = id >> 10;
    int t = (int)(m & (TD - 1));
    long long base = m * (2 * DIE) + c;

    float accf = bf[c];
    float accb = bb[c];
#pragma unroll
    for (int k = 0; k < 7; k++) {
        float w = wf[c * 7 + k];
        float v = (t - 6 + k >= 0) ? xz[base + (long long)(k - 6) * (2 * DIE)] : 0.f;
        accf = fmaf(v, w, accf);
    }
#pragma unroll
    for (int j = 0; j < 7; j++) {
        float w = wb[c * 7 + (6 - j)];
        float v = (t + 1 + j < TD) ? xz[base + (long long)(j + 1) * (2 * DIE)] : 0.f;
        accb = fmaf(v, w, accb);
    }
    cf[id] = accf;
    cb[id] = accb;
}

// ---------------- combine: shifts + diag + gate -------------------------------
__global__ void combine_k(const float* __restrict__ xz,
                          const float* __restrict__ pf, const float* __restrict__ pb,
                          const float* __restrict__ diag, const float* __restrict__ gate,
                          float* __restrict__ y)
{
    long long id = (long long)blockIdx.x * blockDim.x + threadIdx.x;
    int e = (int)(id & (DIE - 1));
    long long m = id >> 10;
    int t = (int)(m & (TD - 1));

    float yf = (t > 0)      ? pf[id - DIE] : 0.f;
    float yb = (t < TD - 1) ? pb[id]       : 0.f;
    float xp = xz[m * (2 * DIE) + e];
    float z  = xz[m * (2 * DIE) + DIE + e];
    y[id] = (yf + yb + xp * diag[e]) * silu_f(z) * gate[0];
}

// ---------------- residual + LayerNorm(512) -----------------------------------
__device__ __forceinline__ float warp_sum(float v) {
#pragma unroll
    for (int o = 16; o > 0; o >>= 1) v += __shfl_down_sync(0xffffffffu, v, o);
    return v;
}

__global__ void ln_kernel(const float* __restrict__ x, const float* __restrict__ o,
                          const float* __restrict__ g, const float* __restrict__ b,
                          float* __restrict__ out)
{
    const int m = blockIdx.x;
    const int tid = threadIdx.x;
    const size_t base = (size_t)m * DD;

    float4 xv = ((const float4*)(x + base))[tid];
    float4 ov = ((const float4*)(o + base))[tid];
    float4 h = make_float4(xv.x + ov.x, xv.y + ov.y, xv.z + ov.z, xv.w + ov.w);

    float s  = h.x + h.y + h.z + h.w;
    float ss = h.x * h.x + h.y * h.y + h.z * h.z + h.w * h.w;

    __shared__ float sh[4], sh2[4];
    float ws  = warp_sum(s);
    float wss = warp_sum(ss);
    if ((tid & 31) == 0) { sh[tid >> 5] = ws; sh2[tid >> 5] = wss; }
    __syncthreads();
    if (tid < 32) {
        float a  = (tid < 4) ? sh[tid]  : 0.f;
        float a2 = (tid < 4) ? sh2[tid] : 0.f;
        a  = warp_sum(a);
        a2 = warp_sum(a2);
        if (tid == 0) { sh[0] = a; sh2[0] = a2; }
    }
    __syncthreads();

    float mu  = sh[0] * (1.f / DD);
    float var = sh2[0] * (1.f / DD) - mu * mu;
    float inv = rsqrtf(var + LN_EPS);

    float4 gv = ((const float4*)g)[tid];
    float4 bv = ((const float4*)b)[tid];
    float4 r;
    r.x = (h.x - mu) * inv * gv.x + bv.x;
    r.y = (h.y - mu) * inv * gv.y + bv.y;
    r.z = (h.z - mu) * inv * gv.z + bv.z;
    r.w = (h.w - mu) * inv * gv.w + bv.w;
    ((float4*)(out + base))[tid] = r;
}

// ---------------- launch ------------------------------------------------------
#define GEMM_SMEM (16384 * 4)   // 64 KB

extern "C" void kernel_launch(void* const* d_in, const int* in_sizes, int n_in,
                              void* d_out, int out_size)
{
    const float* x          = (const float*)d_in[0];
    const float* in_proj_w  = (const float*)d_in[1];
    const float* conv_fwd_w = (const float*)d_in[2];
    const float* conv_fwd_b = (const float*)d_in[3];
    const float* proj_fwd_w = (const float*)d_in[4];
    const float* proj_fwd_b = (const float*)d_in[5];
    const float* conv_bwd_w = (const float*)d_in[6];
    const float* conv_bwd_b = (const float*)d_in[7];
    const float* proj_bwd_w = (const float*)d_in[8];
    const float* proj_bwd_b = (const float*)d_in[9];
    const float* diag       = (const float*)d_in[10];
    const float* gate       = (const float*)d_in[11];
    const float* out_proj_w = (const float*)d_in[12];
    const float* ln_g       = (const float*)d_in[13];
    const float* ln_b       = (const float*)d_in[14];

    float *xz, *cf, *cb, *pf, *pb, *y, *o;
    cudaGetSymbolAddress((void**)&xz, g_xz);
    cudaGetSymbolAddress((void**)&cf, g_cf);
    cudaGetSymbolAddress((void**)&cb, g_cb);
    cudaGetSymbolAddress((void**)&pf, g_pf);
    cudaGetSymbolAddress((void**)&pb, g_pb);
    cudaGetSymbolAddress((void**)&y,  g_y);
    cudaGetSymbolAddress((void**)&o,  g_o);

    cudaFuncSetAttribute(gemm_mma<0>, cudaFuncAttributeMaxDynamicSharedMemorySize, GEMM_SMEM);
    cudaFuncSetAttribute(gemm_mma<1>, cudaFuncAttributeMaxDynamicSharedMemorySize, GEMM_SMEM);

    // 1) xz = x @ in_proj_w^T          (32768 x 2048, K=512)
    gemm_mma<0><<<dim3(2048 / 128, NROWS / 128), 256, GEMM_SMEM>>>(
        x, in_proj_w, nullptr, xz, NROWS, 2048, DD);
    // 2) both depthwise convs
    conv_dw<<<(NROWS * DIE) / 256, 256>>>(xz, conv_fwd_w, conv_fwd_b,
                                          conv_bwd_w, conv_bwd_b, cf, cb);
    // 3) pf = silu(cf @ proj_fwd_w^T + b)
    gemm_mma<1><<<dim3(DIE / 128, NROWS / 128), 256, GEMM_SMEM>>>(
        cf, proj_fwd_w, proj_fwd_b, pf, NROWS, DIE, DIE);
    // 4) pb = silu(cb @ proj_bwd_w^T + b)
    gemm_mma<1><<<dim3(DIE / 128, NROWS / 128), 256, GEMM_SMEM>>>(
        cb, proj_bwd_w, proj_bwd_b, pb, NROWS, DIE, DIE);
    // 5) y = (shift(pf) + mask(pb) + x_proj*diag) * silu(z) * gate
    combine_k<<<(NROWS * DIE) / 256, 256>>>(xz, pf, pb, diag, gate, y);
    // 6) o = y @ out_proj_w^T          (32768 x 512, K=1024)
    gemm_mma<0><<<dim3(DD / 128, NROWS / 128), 256, GEMM_SMEM>>>(
        y, out_proj_w, nullptr, o, NROWS, DD, DIE);
    // 7) out = LayerNorm(x + o)
    ln_kernel<<<NROWS, 128>>>(x, o, ln_g, ln_b, (float*)d_out);
}

// round 4
// speedup vs baseline: 3.9518x; 1.0236x over previous
#include <cuda_runtime.h>
#include <cstdint>

// Problem constants
#define BD    8
#define TD    4096
#define DD    512
#define DIE   1024          // DI
#define NROWS (BD*TD)       // 32768
#define LN_EPS 1e-5f

// ---------------- scratch (no cudaMalloc allowed) ----------------
__device__ float g_xz[(size_t)NROWS * 2 * DIE];
__device__ float g_cf[(size_t)NROWS * DIE];
__device__ float g_cb[(size_t)NROWS * DIE];
__device__ float g_pf[(size_t)NROWS * DIE];
__device__ float g_pb[(size_t)NROWS * DIE];
__device__ float g_y [(size_t)NROWS * DIE];
__device__ float g_o [(size_t)NROWS * DD];

__device__ __forceinline__ float silu_f(float v) {
    return v / (1.f + __expf(-v));
}

__device__ __forceinline__ uint32_t f2tf32(float f) {
    uint32_t u;
    asm("cvt.rna.tf32.f32 %0, %1;" : "=r"(u) : "f"(f));
    return u;
}

__device__ __forceinline__ void mma_tf32(float* c, const uint4& a,
                                         uint32_t b0, uint32_t b1) {
    asm volatile(
        "mma.sync.aligned.m16n8k8.row.col.f32.tf32.tf32.f32 "
        "{%0,%1,%2,%3}, {%4,%5,%6,%7}, {%8,%9}, {%0,%1,%2,%3};"
        : "+f"(c[0]), "+f"(c[1]), "+f"(c[2]), "+f"(c[3])
        : "r"(a.x), "r"(a.y), "r"(a.z), "r"(a.w), "r"(b0), "r"(b1));
}

// =============== tf32 mma.sync GEMM: C[M,N] = A[M,K] * B[N,K]^T ===============
// 128x256x32 block, 512 threads, 16 warps (4M x 4N), warp tile 32x64.
// Fragment-major smem layout (per 32-K chunk):
//   A word = Abase + ((mt*4 + s)*32 + laneA)*4 + regA           (4096 w / buf)
//   B word = Bbase + ((pj*4 + s)*32 + laneB)*4 + regB           (8192 w / buf)
// element (r,k): s=k>>3, d=k&3 (within float4 group kg=k>>2, s=kg>>1),
//   A: mt=r>>4, rr=r&15, laneA=(((rr&7)<<2)|d)^s = ((rr&7)<<2)|(d^s),
//      regA=(rr>>3)|((kg&1)<<1)
//   B: nt=r>>3, nn=r&7, pj=nt>>1, laneB=(nn<<2)|(d^s), regB=((nt&1)<<1)|(kg&1)
// Compute side: LDS.128 at ((blk*4+s)*32 + (l^s))*4 -> conflict-free.
template<int EPI>
__global__ void __launch_bounds__(512, 1)
gemm_mma(const float* __restrict__ A, const float* __restrict__ B,
         const float* __restrict__ bias, float* __restrict__ C,
         int M, int N, int K)
{
    extern __shared__ uint32_t sm[];
    // words: buf0 [A:0..4095 | B:4096..12287], buf1 [12288.. | 16384..24575]
    const int tid = threadIdx.x;
    const int wid = tid >> 5, l = tid & 31;
    const int wm = wid >> 2, wn = wid & 3;
    const int g = l >> 2, q = l & 3;

    const size_t row0 = (size_t)blockIdx.y * 128;
    const size_t col0 = (size_t)blockIdx.x * 256;

    const float* Ag = A + row0 * (size_t)K;
    const float* Bg = B + col0 * (size_t)K;

    // ---- per-thread load/store invariants
    // A: 128 rows x 8 float4-groups = 1024 units -> 2 per thread
    // B: 256 rows x 8 = 2048 units -> 4 per thread
    size_t offA[2], offB[4];
    uint32_t wA[2], wB[4];
    int sA[2], sB[4];
#pragma unroll
    for (int i = 0; i < 2; i++) {
        int idx = tid + i * 512;
        int r = idx >> 3, kg = idx & 7, s = kg >> 1;
        offA[i] = (size_t)r * K + kg * 4;
        int mt = r >> 4, rr = r & 15;
        int regA = (rr >> 3) | ((kg & 1) << 1);
        wA[i] = ((mt * 4 + s) * 32 + ((rr & 7) << 2)) * 4 + regA;
        sA[i] = s;
    }
#pragma unroll
    for (int i = 0; i < 4; i++) {
        int idx = tid + i * 512;
        int r = idx >> 3, kg = idx & 7, s = kg >> 1;
        offB[i] = (size_t)r * K + kg * 4;
        int nt = r >> 3, nn = r & 7;
        int regB = ((nt & 1) << 1) | (kg & 1);
        wB[i] = (((nt >> 1) * 4 + s) * 32 + (nn << 2)) * 4 + regB;
        sB[i] = s;
    }

    float4 stgA[2], stgB[4];
    float acc[2][8][4];
#pragma unroll
    for (int mi = 0; mi < 2; mi++)
#pragma unroll
        for (int j = 0; j < 8; j++)
#pragma unroll
            for (int t = 0; t < 4; t++) acc[mi][j][t] = 0.f;

    const int NC = K >> 5;

    // ---- load + store chunk 0 into buffer 0
#pragma unroll
    for (int i = 0; i < 2; i++) stgA[i] = *(const float4*)(Ag + offA[i]);
#pragma unroll
    for (int i = 0; i < 4; i++) stgB[i] = *(const float4*)(Bg + offB[i]);
#pragma unroll
    for (int i = 0; i < 2; i++) {
        const float* v = (const float*)&stgA[i];
#pragma unroll
        for (int d = 0; d < 4; d++)
            sm[wA[i] + ((d ^ sA[i]) << 2)] = f2tf32(v[d]);
    }
#pragma unroll
    for (int i = 0; i < 4; i++) {
        const float* v = (const float*)&stgB[i];
#pragma unroll
        for (int d = 0; d < 4; d++)
            sm[4096 + wB[i] + ((d ^ sB[i]) << 2)] = f2tf32(v[d]);
    }
    __syncthreads();

    for (int c = 0; c < NC; ++c) {
        // prefetch next chunk from gmem
        if (c + 1 < NC) {
            const float* Ag2 = Ag + (size_t)(c + 1) * 32;
            const float* Bg2 = Bg + (size_t)(c + 1) * 32;
#pragma unroll
            for (int i = 0; i < 2; i++) stgA[i] = *(const float4*)(Ag2 + offA[i]);
#pragma unroll
            for (int i = 0; i < 4; i++) stgB[i] = *(const float4*)(Bg2 + offB[i]);
        }
        // compute on buffer c&1
        const uint32_t* As = sm + (c & 1) * 12288;
        const uint32_t* Bs = As + 4096;
#pragma unroll
        for (int s = 0; s < 4; s++) {
            const int ls = l ^ s;
            uint4 af[2], bf[4];
#pragma unroll
            for (int mi = 0; mi < 2; mi++) {
                int mt = wm * 2 + mi;
                af[mi] = *(const uint4*)&As[((mt * 4 + s) * 32 + ls) * 4];
            }
#pragma unroll
            for (int jj = 0; jj < 4; jj++) {
                int pj = wn * 4 + jj;
                bf[jj] = *(const uint4*)&Bs[((pj * 4 + s) * 32 + ls) * 4];
            }
#pragma unroll
            for (int mi = 0; mi < 2; mi++)
#pragma unroll
                for (int jj = 0; jj < 4; jj++) {
                    mma_tf32(acc[mi][jj * 2],     af[mi], bf[jj].x, bf[jj].y);
                    mma_tf32(acc[mi][jj * 2 + 1], af[mi], bf[jj].z, bf[jj].w);
                }
        }
        // store next chunk to other buffer
        if (c + 1 < NC) {
            uint32_t* Ad = sm + ((c + 1) & 1) * 12288;
            uint32_t* Bd = Ad + 4096;
#pragma unroll
            for (int i = 0; i < 2; i++) {
                const float* v = (const float*)&stgA[i];
#pragma unroll
                for (int d = 0; d < 4; d++)
                    Ad[wA[i] + ((d ^ sA[i]) << 2)] = f2tf32(v[d]);
            }
#pragma unroll
            for (int i = 0; i < 4; i++) {
                const float* v = (const float*)&stgB[i];
#pragma unroll
                for (int d = 0; d < 4; d++)
                    Bd[wB[i] + ((d ^ sB[i]) << 2)] = f2tf32(v[d]);
            }
        }
        __syncthreads();
    }

    // ---- epilogue: acc[mi][j] covers rows row0+wm*32+mi*16+{g,g+8},
    //      cols col0+wn*64+j*8+{q*2, q*2+1}
#pragma unroll
    for (int mi = 0; mi < 2; mi++) {
        size_t r1 = row0 + wm * 32 + mi * 16 + g;
#pragma unroll
        for (int j = 0; j < 8; j++) {
            size_t col = col0 + wn * 64 + j * 8 + q * 2;
            float v00 = acc[mi][j][0], v01 = acc[mi][j][1];
            float v10 = acc[mi][j][2], v11 = acc[mi][j][3];
            if (EPI == 1) {
                float2 bb = *(const float2*)(bias + col);
                v00 = silu_f(v00 + bb.x); v01 = silu_f(v01 + bb.y);
                v10 = silu_f(v10 + bb.x); v11 = silu_f(v11 + bb.y);
            }
            *(float2*)(C + r1 * N + col)       = make_float2(v00, v01);
            *(float2*)(C + (r1 + 8) * N + col) = make_float2(v10, v11);
        }
    }
}

// ---------------- fused depthwise causal (fwd) + anti-causal (bwd) conv ----------
__global__ void conv_dw(const float* __restrict__ xz,
                        const float* __restrict__ wf, const float* __restrict__ bf,
                        const float* __restrict__ wb, const float* __restrict__ bb,
                        float* __restrict__ cf, float* __restrict__ cb)
{
    long long id = (long long)blockIdx.x * blockDim.x + threadIdx.x;
    int c = (int)(id & (DIE - 1));
    long long m = id >> 10;
    int t = (int)(m & (TD - 1));
    long long base = m * (2 * DIE) + c;

    float accf = bf[c];
    float accb = bb[c];
#pragma unroll
    for (int k = 0; k < 7; k++) {
        float w = wf[c * 7 + k];
        float v = (t - 6 + k >= 0) ? xz[base + (long long)(k - 6) * (2 * DIE)] : 0.f;
        accf = fmaf(v, w, accf);
    }
#pragma unroll
    for (int j = 0; j < 7; j++) {
        float w = wb[c * 7 + (6 - j)];
        float v = (t + 1 + j < TD) ? xz[base + (long long)(j + 1) * (2 * DIE)] : 0.f;
        accb = fmaf(v, w, accb);
    }
    cf[id] = accf;
    cb[id] = accb;
}

// ---------------- combine: shifts + diag + gate -------------------------------
__global__ void combine_k(const float* __restrict__ xz,
                          const float* __restrict__ pf, const float* __restrict__ pb,
                          const float* __restrict__ diag, const float* __restrict__ gate,
                          float* __restrict__ y)
{
    long long id = (long long)blockIdx.x * blockDim.x + threadIdx.x;
    int e = (int)(id & (DIE - 1));
    long long m = id >> 10;
    int t = (int)(m & (TD - 1));

    float yf = (t > 0)      ? pf[id - DIE] : 0.f;
    float yb = (t < TD - 1) ? pb[id]       : 0.f;
    float xp = xz[m * (2 * DIE) + e];
    float z  = xz[m * (2 * DIE) + DIE + e];
    y[id] = (yf + yb + xp * diag[e]) * silu_f(z) * gate[0];
}

// ---------------- residual + LayerNorm(512) -----------------------------------
__device__ __forceinline__ float warp_sum(float v) {
#pragma unroll
    for (int o = 16; o > 0; o >>= 1) v += __shfl_down_sync(0xffffffffu, v, o);
    return v;
}

__global__ void ln_kernel(const float* __restrict__ x, const float* __restrict__ o,
                          const float* __restrict__ g, const float* __restrict__ b,
                          float* __restrict__ out)
{
    const int m = blockIdx.x;
    const int tid = threadIdx.x;
    const size_t base = (size_t)m * DD;

    float4 xv = ((const float4*)(x + base))[tid];
    float4 ov = ((const float4*)(o + base))[tid];
    float4 h = make_float4(xv.x + ov.x, xv.y + ov.y, xv.z + ov.z, xv.w + ov.w);

    float s  = h.x + h.y + h.z + h.w;
    float ss = h.x * h.x + h.y * h.y + h.z * h.z + h.w * h.w;

    __shared__ float sh[4], sh2[4];
    float ws  = warp_sum(s);
    float wss = warp_sum(ss);
    if ((tid & 31) == 0) { sh[tid >> 5] = ws; sh2[tid >> 5] = wss; }
    __syncthreads();
    if (tid < 32) {
        float a  = (tid < 4) ? sh[tid]  : 0.f;
        float a2 = (tid < 4) ? sh2[tid] : 0.f;
        a  = warp_sum(a);
        a2 = warp_sum(a2);
        if (tid == 0) { sh[0] = a; sh2[0] = a2; }
    }
    __syncthreads();

    float mu  = sh[0] * (1.f / DD);
    float var = sh2[0] * (1.f / DD) - mu * mu;
    float inv = rsqrtf(var + LN_EPS);

    float4 gv = ((const float4*)g)[tid];
    float4 bv = ((const float4*)b)[tid];
    float4 r;
    r.x = (h.x - mu) * inv * gv.x + bv.x;
    r.y = (h.y - mu) * inv * gv.y + bv.y;
    r.z = (h.z - mu) * inv * gv.z + bv.z;
    r.w = (h.w - mu) * inv * gv.w + bv.w;
    ((float4*)(out + base))[tid] = r;
}

// ---------------- launch ------------------------------------------------------
#define GEMM_SMEM (24576 * 4)   // 96 KB

extern "C" void kernel_launch(void* const* d_in, const int* in_sizes, int n_in,
                              void* d_out, int out_size)
{
    const float* x          = (const float*)d_in[0];
    const float* in_proj_w  = (const float*)d_in[1];
    const float* conv_fwd_w = (const float*)d_in[2];
    const float* conv_fwd_b = (const float*)d_in[3];
    const float* proj_fwd_w = (const float*)d_in[4];
    const float* proj_fwd_b = (const float*)d_in[5];
    const float* conv_bwd_w = (const float*)d_in[6];
    const float* conv_bwd_b = (const float*)d_in[7];
    const float* proj_bwd_w = (const float*)d_in[8];
    const float* proj_bwd_b = (const float*)d_in[9];
    const float* diag       = (const float*)d_in[10];
    const float* gate       = (const float*)d_in[11];
    const float* out_proj_w = (const float*)d_in[12];
    const float* ln_g       = (const float*)d_in[13];
    const float* ln_b       = (const float*)d_in[14];

    float *xz, *cf, *cb, *pf, *pb, *y, *o;
    cudaGetSymbolAddress((void**)&xz, g_xz);
    cudaGetSymbolAddress((void**)&cf, g_cf);
    cudaGetSymbolAddress((void**)&cb, g_cb);
    cudaGetSymbolAddress((void**)&pf, g_pf);
    cudaGetSymbolAddress((void**)&pb, g_pb);
    cudaGetSymbolAddress((void**)&y,  g_y);
    cudaGetSymbolAddress((void**)&o,  g_o);

    cudaFuncSetAttribute(gemm_mma<0>, cudaFuncAttributeMaxDynamicSharedMemorySize, GEMM_SMEM);
    cudaFuncSetAttribute(gemm_mma<1>, cudaFuncAttributeMaxDynamicSharedMemorySize, GEMM_SMEM);

    // 1) xz = x @ in_proj_w^T          (32768 x 2048, K=512)
    gemm_mma<0><<<dim3(2048 / 256, NROWS / 128), 512, GEMM_SMEM>>>(
        x, in_proj_w, nullptr, xz, NROWS, 2048, DD);
    // 2) both depthwise convs
    conv_dw<<<(NROWS * DIE) / 256, 256>>>(xz, conv_fwd_w, conv_fwd_b,
                                          conv_bwd_w, conv_bwd_b, cf, cb);
    // 3) pf = silu(cf @ proj_fwd_w^T + b)
    gemm_mma<1><<<dim3(DIE / 256, NROWS / 128), 512, GEMM_SMEM>>>(
        cf, proj_fwd_w, proj_fwd_b, pf, NROWS, DIE, DIE);
    // 4) pb = silu(cb @ proj_bwd_w^T + b)
    gemm_mma<1><<<dim3(DIE / 256, NROWS / 128), 512, GEMM_SMEM>>>(
        cb, proj_bwd_w, proj_bwd_b, pb, NROWS, DIE, DIE);
    // 5) y = (shift(pf) + mask(pb) + x_proj*diag) * silu(z) * gate
    combine_k<<<(NROWS * DIE) / 256, 256>>>(xz, pf, pb, diag, gate, y);
    // 6) o = y @ out_proj_w^T          (32768 x 512, K=1024)
    gemm_mma<0><<<dim3(DD / 256, NROWS / 128), 512, GEMM_SMEM>>>(
        y, out_proj_w, nullptr, o, NROWS, DD, DIE);
    // 7) out = LayerNorm(x + o)
    ln_kernel<<<NROWS, 128>>>(x, o, ln_g, ln_b, (float*)d_out);
}

// round 5
// speedup vs baseline: 5.9117x; 1.4960x over previous
#include <cuda_runtime.h>
#include <cstdint>

// Problem constants
#define BD    8
#define TD    4096
#define DD    512
#define DIE   1024          // DI
#define NROWS (BD*TD)       // 32768
#define LN_EPS 1e-5f

// ---------------- scratch (no cudaMalloc allowed) ----------------
__device__ float g_xz[(size_t)NROWS * 2 * DIE];
__device__ float g_cf[(size_t)NROWS * DIE];
__device__ float g_cb[(size_t)NROWS * DIE];
__device__ float g_pf[(size_t)NROWS * DIE];
__device__ float g_pb[(size_t)NROWS * DIE];
__device__ float g_y [(size_t)NROWS * DIE];
__device__ float g_o [(size_t)NROWS * DD];
__device__ float g_xr[(size_t)NROWS * DD];          // tf32-rounded x
__device__ float g_w1[(size_t)2 * DIE * DD];        // rounded in_proj_w
__device__ float g_wf[(size_t)DIE * DIE];           // rounded proj_fwd_w
__device__ float g_wb[(size_t)DIE * DIE];           // rounded proj_bwd_w
__device__ float g_wo[(size_t)DD * DIE];            // rounded out_proj_w

__device__ __forceinline__ float silu_f(float v) {
    return v / (1.f + __expf(-v));
}

__device__ __forceinline__ float tf32r(float f) {
    uint32_t u;
    asm("cvt.rna.tf32.f32 %0, %1;" : "=r"(u) : "f"(f));
    return __uint_as_float(u);
}

__device__ __forceinline__ uint32_t smem_to_u32(const void* p) {
    uint32_t a;
    asm("{ .reg .u64 t; cvta.to.shared.u64 t, %1; cvt.u32.u64 %0, t; }" : "=r"(a) : "l"(p));
    return a;
}

__device__ __forceinline__ void mma_tf32(float* c, const uint32_t* a,
                                         uint32_t b0, uint32_t b1) {
    asm volatile(
        "mma.sync.aligned.m16n8k8.row.col.f32.tf32.tf32.f32 "
        "{%0,%1,%2,%3}, {%4,%5,%6,%7}, {%8,%9}, {%0,%1,%2,%3};"
        : "+f"(c[0]), "+f"(c[1]), "+f"(c[2]), "+f"(c[3])
        : "r"(a[0]), "r"(a[1]), "r"(a[2]), "r"(a[3]), "r"(b0), "r"(b1));
}

__device__ __forceinline__ void ldsm4(uint32_t* r, uint32_t addr) {
    asm volatile("ldmatrix.sync.aligned.m8n8.x4.shared.b16 {%0,%1,%2,%3}, [%4];"
        : "=r"(r[0]), "=r"(r[1]), "=r"(r[2]), "=r"(r[3]) : "r"(addr));
}

#define CP16(dst, src) \
    asm volatile("cp.async.cg.shared.global [%0], [%1], 16;" :: "r"(dst), "l"(src))
#define CP_COMMIT() asm volatile("cp.async.commit_group;" ::: "memory")
#define CP_WAIT1()  asm volatile("cp.async.wait_group 1;" ::: "memory")

// =============== tf32 GEMM: C[M,N] = A[M,K] * B[N,K]^T (inputs pre-rounded) ===
// 128x128x32 CTA tile, 128 threads, 4 warps (2M x 2N), warp tile 64x64.
// 3-stage cp.async pipeline. Smem per stage: A 16KB + B 16KB (K-major, 128B rows,
// 16B-group swizzle: group' = kg ^ (row&7)). Fragments via ldmatrix.x4 (b16 mover
// on tf32 data: 8x8 b16 block == 8x4 u32 block; non-trans layout matches both the
// mma A-fragment (row=l>>2,col=l&3) and B[n][k] row-major).
#define ST_STRIDE 32768u
template<int EPI>
__global__ void __launch_bounds__(128, 2)
gemm_tc(const float* __restrict__ A, const float* __restrict__ B,
        const float* __restrict__ bias, float* __restrict__ C,
        int M, int N, int K)
{
    extern __shared__ char smem[];
    const uint32_t al = smem_to_u32(smem);

    const int tid = threadIdx.x;
    const int wid = tid >> 5, l = tid & 31;
    const int wm = wid >> 1, wn = wid & 1;

    const size_t row0 = (size_t)blockIdx.y * 128;
    const size_t col0 = (size_t)blockIdx.x * 128;

    // ---- cp.async invariants: thread -> (row = tid>>3 + 16i, kgroup = tid&7)
    const int ldr = tid >> 3;        // 0..15
    const int ldkg = tid & 7;
    const uint32_t sg = (uint32_t)(ldkg ^ (ldr & 7)) << 4;   // swizzled 16B group
    const float* gA = A + (row0 + ldr) * (size_t)K + ldkg * 4;
    const float* gB = B + (col0 + ldr) * (size_t)K + ldkg * 4;
    const uint32_t sA0 = al + ldr * 128 + sg;
    const uint32_t sB0 = al + 16384 + ldr * 128 + sg;

    // ---- fragment address invariants
    const uint32_t lr = l & 7, g01 = (l >> 3) & 1, g2 = (uint32_t)l >> 4;
    uint32_t aRow[4], bRow[4];
#pragma unroll
    for (int mi = 0; mi < 4; mi++)
        aRow[mi] = al + (uint32_t)(wm * 64 + mi * 16 + g01 * 8 + lr) * 128;
#pragma unroll
    for (int p = 0; p < 4; p++)
        bRow[p] = al + 16384 + (uint32_t)(wn * 64 + p * 16 + g2 * 8 + lr) * 128;

    float acc[4][8][4];
#pragma unroll
    for (int mi = 0; mi < 4; mi++)
#pragma unroll
        for (int j = 0; j < 8; j++)
#pragma unroll
            for (int t = 0; t < 4; t++) acc[mi][j][t] = 0.f;

    const int NC = K >> 5;

    // ---- prologue: load chunks 0,1 into stages 0,1
#pragma unroll
    for (int s = 0; s < 2; s++) {
        const float* pa = gA + s * 32;
        const float* pb = gB + s * 32;
        uint32_t da = sA0 + s * ST_STRIDE;
        uint32_t db = sB0 + s * ST_STRIDE;
#pragma unroll
        for (int i = 0; i < 8; i++) {
            CP16(da + i * 2048, pa + (size_t)i * 16 * K);
            CP16(db + i * 2048, pb + (size_t)i * 16 * K);
        }
        CP_COMMIT();
    }

    for (int c = 0; c < NC; ++c) {
        CP_WAIT1();
        __syncthreads();
        if (c + 2 < NC) {
            const int st = (c + 2) % 3;
            const float* pa = gA + (size_t)(c + 2) * 32;
            const float* pb = gB + (size_t)(c + 2) * 32;
            uint32_t da = sA0 + st * ST_STRIDE;
            uint32_t db = sB0 + st * ST_STRIDE;
#pragma unroll
            for (int i = 0; i < 8; i++) {
                CP16(da + i * 2048, pa + (size_t)i * 16 * K);
                CP16(db + i * 2048, pb + (size_t)i * 16 * K);
            }
        }
        CP_COMMIT();

        const uint32_t stOff = (uint32_t)(c % 3) * ST_STRIDE;
#pragma unroll
        for (int s = 0; s < 4; s++) {
            const uint32_t aOff = stOff + ((((uint32_t)(2 * s) + g2) ^ lr) << 4);
            const uint32_t bOff = stOff + ((((uint32_t)(2 * s) + g01) ^ lr) << 4);
            uint32_t af[4][4], bf[4][4];
#pragma unroll
            for (int mi = 0; mi < 4; mi++) ldsm4(af[mi], aRow[mi] + aOff);
#pragma unroll
            for (int p = 0; p < 4; p++)  ldsm4(bf[p], bRow[p] + bOff);
#pragma unroll
            for (int mi = 0; mi < 4; mi++)
#pragma unroll
                for (int p = 0; p < 4; p++) {
                    mma_tf32(acc[mi][2 * p],     af[mi], bf[p][0], bf[p][1]);
                    mma_tf32(acc[mi][2 * p + 1], af[mi], bf[p][2], bf[p][3]);
                }
        }
    }

    // ---- epilogue: acc[mi][nj] -> rows row0+wm*64+mi*16+{l>>2, +8},
    //      cols col0+wn*64+nj*8+(l&3)*2+{0,1}
    const int gq = l >> 2, qq = l & 3;
#pragma unroll
    for (int mi = 0; mi < 4; mi++) {
        size_t r1 = row0 + wm * 64 + mi * 16 + gq;
#pragma unroll
        for (int nj = 0; nj < 8; nj++) {
            size_t cc = col0 + wn * 64 + nj * 8 + qq * 2;
            float v00 = acc[mi][nj][0], v01 = acc[mi][nj][1];
            float v10 = acc[mi][nj][2], v11 = acc[mi][nj][3];
            if (EPI == 1) {
                float2 bb = *(const float2*)(bias + cc);
                v00 = silu_f(v00 + bb.x); v01 = silu_f(v01 + bb.y);
                v10 = silu_f(v10 + bb.x); v11 = silu_f(v11 + bb.y);
            }
            *(float2*)(C + r1 * N + cc)       = make_float2(v00, v01);
            *(float2*)(C + (r1 + 8) * N + cc) = make_float2(v10, v11);
        }
    }
}

// ---------------- tf32 pre-round (float4 grid-stride) -------------------------
__global__ void round_tf32(const float* __restrict__ src, float* __restrict__ dst,
                           long long n4)
{
    long long i = (long long)blockIdx.x * blockDim.x + threadIdx.x;
    if (i < n4) {
        float4 v = ((const float4*)src)[i];
        v.x = tf32r(v.x); v.y = tf32r(v.y); v.z = tf32r(v.z); v.w = tf32r(v.w);
        ((float4*)dst)[i] = v;
    }
}

// ---------------- fused depthwise causal (fwd) + anti-causal (bwd) conv ----------
// outputs rounded to tf32 (they feed the proj GEMMs)
__global__ void conv_dw(const float* __restrict__ xz,
                        const float* __restrict__ wf, const float* __restrict__ bf,
                        const float* __restrict__ wb, const float* __restrict__ bb,
                        float* __restrict__ cf, float* __restrict__ cb)
{
    long long id = (long long)blockIdx.x * blockDim.x + threadIdx.x;
    int c = (int)(id & (DIE - 1));
    long long m = id >> 10;
    int t = (int)(m & (TD - 1));
    long long base = m * (2 * DIE) + c;

    float accf = bf[c];
    float accb = bb[c];
#pragma unroll
    for (int k = 0; k < 7; k++) {
        float w = wf[c * 7 + k];
        float v = (t - 6 + k >= 0) ? xz[base + (long long)(k - 6) * (2 * DIE)] : 0.f;
        accf = fmaf(v, w, accf);
    }
#pragma unroll
    for (int j = 0; j < 7; j++) {
        float w = wb[c * 7 + (6 - j)];
        float v = (t + 1 + j < TD) ? xz[base + (long long)(j + 1) * (2 * DIE)] : 0.f;
        accb = fmaf(v, w, accb);
    }
    cf[id] = tf32r(accf);
    cb[id] = tf32r(accb);
}

// ---------------- combine: shifts + diag + gate (output rounded) ---------------
__global__ void combine_k(const float* __restrict__ xz,
                          const float* __restrict__ pf, const float* __restrict__ pb,
                          const float* __restrict__ diag, const float* __restrict__ gate,
                          float* __restrict__ y)
{
    long long id = (long long)blockIdx.x * blockDim.x + threadIdx.x;
    int e = (int)(id & (DIE - 1));
    long long m = id >> 10;
    int t = (int)(m & (TD - 1));

    float yf = (t > 0)      ? pf[id - DIE] : 0.f;
    float yb = (t < TD - 1) ? pb[id]       : 0.f;
    float xp = xz[m * (2 * DIE) + e];
    float z  = xz[m * (2 * DIE) + DIE + e];
    y[id] = tf32r((yf + yb + xp * diag[e]) * silu_f(z) * gate[0]);
}

// ---------------- residual + LayerNorm(512) -----------------------------------
__device__ __forceinline__ float warp_sum(float v) {
#pragma unroll
    for (int o = 16; o > 0; o >>= 1) v += __shfl_down_sync(0xffffffffu, v, o);
    return v;
}

__global__ void ln_kernel(const float* __restrict__ x, const float* __restrict__ o,
                          const float* __restrict__ g, const float* __restrict__ b,
                          float* __restrict__ out)
{
    const int m = blockIdx.x;
    const int tid = threadIdx.x;
    const size_t base = (size_t)m * DD;

    float4 xv = ((const float4*)(x + base))[tid];
    float4 ov = ((const float4*)(o + base))[tid];
    float4 h = make_float4(xv.x + ov.x, xv.y + ov.y, xv.z + ov.z, xv.w + ov.w);

    float s  = h.x + h.y + h.z + h.w;
    float ss = h.x * h.x + h.y * h.y + h.z * h.z + h.w * h.w;

    __shared__ float sh[4], sh2[4];
    float ws  = warp_sum(s);
    float wss = warp_sum(ss);
    if ((tid & 31) == 0) { sh[tid >> 5] = ws; sh2[tid >> 5] = wss; }
    __syncthreads();
    if (tid < 32) {
        float a  = (tid < 4) ? sh[tid]  : 0.f;
        float a2 = (tid < 4) ? sh2[tid] : 0.f;
        a  = warp_sum(a);
        a2 = warp_sum(a2);
        if (tid == 0) { sh[0] = a; sh2[0] = a2; }
    }
    __syncthreads();

    float mu  = sh[0] * (1.f / DD);
    float var = sh2[0] * (1.f / DD) - mu * mu;
    float inv = rsqrtf(var + LN_EPS);

    float4 gv = ((const float4*)g)[tid];
    float4 bv = ((const float4*)b)[tid];
    float4 r;
    r.x = (h.x - mu) * inv * gv.x + bv.x;
    r.y = (h.y - mu) * inv * gv.y + bv.y;
    r.z = (h.z - mu) * inv * gv.z + bv.z;
    r.w = (h.w - mu) * inv * gv.w + bv.w;
    ((float4*)(out + base))[tid] = r;
}

// ---------------- launch ------------------------------------------------------
#define GEMM_SMEM (3 * 32768)   // 96 KB

extern "C" void kernel_launch(void* const* d_in, const int* in_sizes, int n_in,
                              void* d_out, int out_size)
{
    const float* x          = (const float*)d_in[0];
    const float* in_proj_w  = (const float*)d_in[1];
    const float* conv_fwd_w = (const float*)d_in[2];
    const float* conv_fwd_b = (const float*)d_in[3];
    const float* proj_fwd_w = (const float*)d_in[4];
    const float* proj_fwd_b = (const float*)d_in[5];
    const float* conv_bwd_w = (const float*)d_in[6];
    const float* conv_bwd_b = (const float*)d_in[7];
    const float* proj_bwd_w = (const float*)d_in[8];
    const float* proj_bwd_b = (const float*)d_in[9];
    const float* diag       = (const float*)d_in[10];
    const float* gate       = (const float*)d_in[11];
    const float* out_proj_w = (const float*)d_in[12];
    const float* ln_g       = (const float*)d_in[13];
    const float* ln_b       = (const float*)d_in[14];

    float *xz, *cf, *cb, *pf, *pb, *y, *o, *xr, *w1, *wf, *wb, *wo;
    cudaGetSymbolAddress((void**)&xz, g_xz);
    cudaGetSymbolAddress((void**)&cf, g_cf);
    cudaGetSymbolAddress((void**)&cb, g_cb);
    cudaGetSymbolAddress((void**)&pf, g_pf);
    cudaGetSymbolAddress((void**)&pb, g_pb);
    cudaGetSymbolAddress((void**)&y,  g_y);
    cudaGetSymbolAddress((void**)&o,  g_o);
    cudaGetSymbolAddress((void**)&xr, g_xr);
    cudaGetSymbolAddress((void**)&w1, g_w1);
    cudaGetSymbolAddress((void**)&wf, g_wf);
    cudaGetSymbolAddress((void**)&wb, g_wb);
    cudaGetSymbolAddress((void**)&wo, g_wo);

    cudaFuncSetAttribute(gemm_tc<0>, cudaFuncAttributeMaxDynamicSharedMemorySize, GEMM_SMEM);
    cudaFuncSetAttribute(gemm_tc<1>, cudaFuncAttributeMaxDynamicSharedMemorySize, GEMM_SMEM);

    // 0) tf32 pre-rounding of all GEMM inputs not produced by our own kernels
    {
        long long n4;
        n4 = (long long)NROWS * DD / 4;
        round_tf32<<<(unsigned)((n4 + 255) / 256), 256>>>(x, xr, n4);
        n4 = (long long)2 * DIE * DD / 4;
        round_tf32<<<(unsigned)((n4 + 255) / 256), 256>>>(in_proj_w, w1, n4);
        n4 = (long long)DIE * DIE / 4;
        round_tf32<<<(unsigned)((n4 + 255) / 256), 256>>>(proj_fwd_w, wf, n4);
        round_tf32<<<(unsigned)((n4 + 255) / 256), 256>>>(proj_bwd_w, wb, n4);
        n4 = (long long)DD * DIE / 4;
        round_tf32<<<(unsigned)((n4 + 255) / 256), 256>>>(out_proj_w, wo, n4);
    }

    // 1) xz = xr @ w1^T          (32768 x 2048, K=512)
    gemm_tc<0><<<dim3(2048 / 128, NROWS / 128), 128, GEMM_SMEM>>>(
        xr, w1, nullptr, xz, NROWS, 2048, DD);
    // 2) both depthwise convs (outputs tf32-rounded)
    conv_dw<<<(NROWS * DIE) / 256, 256>>>(xz, conv_fwd_w, conv_fwd_b,
                                          conv_bwd_w, conv_bwd_b, cf, cb);
    // 3) pf = silu(cf @ wf^T + b)
    gemm_tc<1><<<dim3(DIE / 128, NROWS / 128), 128, GEMM_SMEM>>>(
        cf, wf, proj_fwd_b, pf, NROWS, DIE, DIE);
    // 4) pb = silu(cb @ wb^T + b)
    gemm_tc<1><<<dim3(DIE / 128, NROWS / 128), 128, GEMM_SMEM>>>(
        cb, wb, proj_bwd_b, pb, NROWS, DIE, DIE);
    // 5) y = (shift(pf) + mask(pb) + x_proj*diag) * silu(z) * gate  (rounded)
    combine_k<<<(NROWS * DIE) / 256, 256>>>(xz, pf, pb, diag, gate, y);
    // 6) o = y @ wo^T             (32768 x 512, K=1024)
    gemm_tc<0><<<dim3(DD / 128, NROWS / 128), 128, GEMM_SMEM>>>(
        y, wo, nullptr, o, NROWS, DD, DIE);
    // 7) out = LayerNorm(x + o)
    ln_kernel<<<NROWS, 128>>>(x, o, ln_g, ln_b, (float*)d_out);
}